// round 2
// baseline (speedup 1.0000x reference)
#include <cuda_runtime.h>

#define GRID       2048
#define TPB        256
#define TILE_ROWS  256
#define ROW_W      19   // 18 used floats per row + 1 pad word (odd stride -> conflict-free LDS)

// Per-block partial sums; fully overwritten every launch (graph-deterministic).
__device__ float g_part[GRID];

__device__ __forceinline__ float group_loss3(float ax, float ay, float az,
                                             float bx, float by, float bz,
                                             float cx, float cy, float cz) {
    float ia = rsqrtf(ax * ax + ay * ay + az * az);
    float ib = rsqrtf(bx * bx + by * by + bz * bz);
    float ic = rsqrtf(cx * cx + cy * cy + cz * cz);
    ax *= ia; ay *= ia; az *= ia;
    bx *= ib; by *= ib; bz *= ib;
    cx *= ic; cy *= ic; cz *= ic;

    float daa = ax * ax + ay * ay + az * az - 1.0f;
    float dbb = bx * bx + by * by + bz * bz - 1.0f;
    float dcc = cx * cx + cy * cy + cz * cz - 1.0f;
    float dab = ax * bx + ay * by + az * bz;
    float dac = ax * cx + ay * cy + az * cz;
    float dbc = bx * cx + by * cy + bz * cz;

    return daa * daa + dbb * dbb + dcc * dcc
         + 2.0f * (dab * dab + dac * dac + dbc * dbc);
}

__global__ void __launch_bounds__(TPB) loss_kernel(const float4* __restrict__ in,
                                                   int nrows) {
    __shared__ float s[TILE_ROWS * ROW_W];
    const int tid = threadIdx.x;
    const int ntiles = (nrows + TILE_ROWS - 1) / TILE_ROWS;

    float acc = 0.0f;

    for (int t = blockIdx.x; t < ntiles; t += gridDim.x) {
        const int base_row = t * TILE_ROWS;
        const int rows = min(TILE_ROWS, nrows - base_row);
        const int nf4 = rows * 6;
        const float4* __restrict__ g4 = in + (size_t)base_row * 6;

        __syncthreads();  // previous tile's smem reads complete before overwrite

        // Coalesced float4 loads; scatter only the 3 used components per float4.
        // float4 index i: row = i/6, col = i%6; word (col*4 + 0) of the row is
        // the unused component-0 -> skip it; used words compress to col*3 + {0,1,2}.
        #pragma unroll
        for (int j = 0; j < 6; j++) {
            int i = tid + TPB * j;
            if (i < nf4) {
                float4 v = g4[i];
                int row = i / 6;
                int col = i - row * 6;
                float* p = &s[row * ROW_W + col * 3];
                p[0] = v.y;
                p[1] = v.z;
                p[2] = v.w;
            }
        }
        __syncthreads();

        if (tid < rows) {
            const float* r = &s[tid * ROW_W];
            acc += group_loss3(r[0],  r[1],  r[2],
                               r[3],  r[4],  r[5],
                               r[6],  r[7],  r[8]);
            acc += group_loss3(r[9],  r[10], r[11],
                               r[12], r[13], r[14],
                               r[15], r[16], r[17]);
        }
    }

    // Block reduction (reuse smem after a sync).
    #pragma unroll
    for (int off = 16; off > 0; off >>= 1)
        acc += __shfl_xor_sync(0xFFFFFFFFu, acc, off);

    __syncthreads();
    const int lane = tid & 31;
    const int warp = tid >> 5;
    if (lane == 0) s[warp] = acc;
    __syncthreads();

    if (warp == 0) {
        acc = (lane < TPB / 32) ? s[lane] : 0.0f;
        #pragma unroll
        for (int off = 4; off > 0; off >>= 1)
            acc += __shfl_xor_sync(0xFFFFFFFFu, acc, off);
        if (lane == 0) g_part[blockIdx.x] = acc;
    }
}

__global__ void __launch_bounds__(TPB) finalize_kernel(float* out, int nrows) {
    __shared__ double ws[TPB / 32];
    const int tid = threadIdx.x;

    double a = 0.0;
    for (int i = tid; i < GRID; i += TPB)
        a += (double)g_part[i];

    #pragma unroll
    for (int off = 16; off > 0; off >>= 1)
        a += __shfl_xor_sync(0xFFFFFFFFu, a, off);

    const int lane = tid & 31;
    const int warp = tid >> 5;
    if (lane == 0) ws[warp] = a;
    __syncthreads();

    if (warp == 0) {
        a = (lane < TPB / 32) ? ws[lane] : 0.0;
        #pragma unroll
        for (int off = 4; off > 0; off >>= 1)
            a += __shfl_xor_sync(0xFFFFFFFFu, a, off);
        if (lane == 0) out[0] = (float)(a / (double)nrows);
    }
}

extern "C" void kernel_launch(void* const* d_in, const int* in_sizes, int n_in,
                              void* d_out, int out_size) {
    const float4* in = (const float4*)d_in[0];
    float* out = (float*)d_out;
    int nrows = in_sizes[0] / 24;  // 24 floats per row

    loss_kernel<<<GRID, TPB>>>(in, nrows);
    finalize_kernel<<<1, TPB>>>(out, nrows);
}